// round 10
// baseline (speedup 1.0000x reference)
#include <cuda_runtime.h>
#include <cuda_bf16.h>
#include <cstdint>

#define NTHREADS 256
#define MINBLK   7
#define NBLOCKS  (148 * MINBLK)
#define LVL      64

// Quantize/dequantize (AdaptedEntropyModel):
//   r = x - means
//   pos = clip(searchsorted(cb, r, side='left'), 1, 63)
//   sym = (r - cb[pos-1] <= cb[pos] - r) ? pos-1 : pos
//   y_hat = cb[sym] + means
// Output (out_size == 2N floats): [0..N) = float(sym), [N..2N) = y_hat.
//
// R9: unroll-by-2 grid-stride — all four LDG.128s (x,m for two strided
// positions) issue back-to-back at iteration start (MLP_p1=4, 2x R2/R5),
// with NO loop-carried pipeline registers, so occupancy stays high under
// __launch_bounds__(256,7). Body is the proven cheap search: cb31 register
// probe + 5 lane-replicated conflict-free shared probes + 2 neighbor LDS.
// Stores use .cs (evict-first; outputs are never re-read).

__device__ __forceinline__ void process4(float4 xv, float4 mv,
                                         const float* __restrict__ mycb,
                                         float cb31,
                                         float4& so, float4& yo)
{
    float r[4]  = { xv.x - mv.x, xv.y - mv.y, xv.z - mv.z, xv.w - mv.w };
    float mn[4] = { mv.x, mv.y, mv.z, mv.w };
    float sy[4], yy[4];

    #pragma unroll
    for (int j = 0; j < 4; ++j) {
        const float rv = r[j];
        int pos = (cb31 < rv) ? 32 : 0;
        #pragma unroll
        for (int step = 16; step > 0; step >>= 1) {
            if (mycb[(pos + step - 1) << 5] < rv) pos += step;
        }
        pos = min(max(pos, 1), LVL - 1);       // clip to [1,63] like reference
        float left  = mycb[(pos - 1) << 5];
        float right = mycb[pos << 5];
        bool take_left = (rv - left) <= (right - rv);   // exact reference tie rule
        sy[j] = (float)(take_left ? (pos - 1) : pos);
        yy[j] = (take_left ? left : right) + mn[j];
    }
    so = make_float4(sy[0], sy[1], sy[2], sy[3]);
    yo = make_float4(yy[0], yy[1], yy[2], yy[3]);
}

__global__ void __launch_bounds__(NTHREADS, MINBLK)
quant_dequant_kernel(const float4* __restrict__ x4,
                     const float4* __restrict__ m4,
                     const float*  __restrict__ cb,
                     float* __restrict__ out_sym,
                     float* __restrict__ out_y,
                     int n4, int n)
{
    // Lane-private codebook replicas: entry i for lane l at s_cb[i*32 + l] ->
    // every data-dependent probe hits bank == lane (conflict-free).
    __shared__ float s_cb[LVL * 32];
    for (int i = threadIdx.x; i < LVL * 32; i += NTHREADS)
        s_cb[i] = cb[i >> 5];
    const float cb31 = __ldg(cb + 31);
    __syncthreads();

    const int    lane = threadIdx.x & 31;
    const float* mycb = s_cb + lane;           // mycb[idx*32] == cb[idx]

    const int stride  = gridDim.x * NTHREADS;
    const int i0      = blockIdx.x * NTHREADS + threadIdx.x;

    for (int i = i0; i < n4; i += 2 * stride) {
        const int i2   = i + stride;
        const bool has2 = (i2 < n4);

        // Front-batched loads: 4 independent LDG.128 (MLP_p1 = 4).
        float4 xv1 = x4[i];
        float4 mv1 = m4[i];
        float4 xv2, mv2;
        if (has2) { xv2 = x4[i2]; mv2 = m4[i2]; }

        float4 so, yo;
        process4(xv1, mv1, mycb, cb31, so, yo);
        __stcs((float4*)out_sym + i, so);
        __stcs((float4*)out_y   + i, yo);

        if (has2) {
            process4(xv2, mv2, mycb, cb31, so, yo);
            __stcs((float4*)out_sym + i2, so);
            __stcs((float4*)out_y   + i2, yo);
        }
    }

    // Scalar tail (n not divisible by 4 — not expected here, but safe).
    int tail_start = n4 * 4;
    for (int t = tail_start + i0; t < n; t += stride) {
        const float* xs = (const float*)x4;
        const float* ms = (const float*)m4;
        float mvs = ms[t];
        float rv  = xs[t] - mvs;
        int pos = (cb31 < rv) ? 32 : 0;
        #pragma unroll
        for (int step = 16; step > 0; step >>= 1) {
            if (mycb[(pos + step - 1) << 5] < rv) pos += step;
        }
        pos = min(max(pos, 1), LVL - 1);
        float left  = mycb[(pos - 1) << 5];
        float right = mycb[pos << 5];
        bool take_left = (rv - left) <= (right - rv);
        out_sym[t] = (float)(take_left ? (pos - 1) : pos);
        out_y[t]   = (take_left ? left : right) + mvs;
    }
}

extern "C" void kernel_launch(void* const* d_in, const int* in_sizes, int n_in,
                              void* d_out, int out_size)
{
    const float* x     = (const float*)d_in[0];   // [B,C,H,W] f32
    const float* means = (const float*)d_in[1];   // [B,C,H,W] f32
    const float* cb    = (const float*)d_in[2];   // [64] f32 sorted

    int n  = in_sizes[0];
    int n4 = n >> 2;

    float* out_sym = (float*)d_out;       // first N floats: symbols (exact in f32)
    float* out_y   = out_sym + n;         // next  N floats: y_hat

    quant_dequant_kernel<<<NBLOCKS, NTHREADS>>>(
        (const float4*)x, (const float4*)means, cb, out_sym, out_y, n4, n);
}

// round 11
// speedup vs baseline: 1.0952x; 1.0952x over previous
#include <cuda_runtime.h>
#include <cuda_bf16.h>
#include <cstdint>

#define NTHREADS 256
#define MINBLK   6
#define NBLOCKS  (148 * MINBLK)
#define LVL      64

// Quantize/dequantize (AdaptedEntropyModel):
//   r = x - means
//   pos = clip(searchsorted(cb, r, side='left'), 1, 63)
//   sym = (r - cb[pos-1] <= cb[pos] - r) ? pos-1 : pos
//   y_hat = cb[sym] + means
// Output (out_size == 2N floats): [0..N) = float(sym), [N..2N) = y_hat.
//
// R10: branch-free unroll-by-2. The main loop only runs when BOTH strided
// positions are in range, so all four LDG.128s are unconditional and issue
// back-to-back (true MLP_p1=4; R9's guarded version collapsed to MLP 2).
// Body is the proven cheap search: cb31 register probe + 5 lane-replicated
// conflict-free shared probes + 2 neighbor LDS. Plain STG (as in the best
// config R5). __launch_bounds__(256,6), grid 888 = R5 occupancy.

__device__ __forceinline__ void process4(float4 xv, float4 mv,
                                         const float* __restrict__ mycb,
                                         float cb31,
                                         float4& so, float4& yo)
{
    float r[4]  = { xv.x - mv.x, xv.y - mv.y, xv.z - mv.z, xv.w - mv.w };
    float mn[4] = { mv.x, mv.y, mv.z, mv.w };
    float sy[4], yy[4];

    #pragma unroll
    for (int j = 0; j < 4; ++j) {
        const float rv = r[j];
        int pos = (cb31 < rv) ? 32 : 0;
        #pragma unroll
        for (int step = 16; step > 0; step >>= 1) {
            if (mycb[(pos + step - 1) << 5] < rv) pos += step;
        }
        pos = min(max(pos, 1), LVL - 1);       // clip to [1,63] like reference
        float left  = mycb[(pos - 1) << 5];
        float right = mycb[pos << 5];
        bool take_left = (rv - left) <= (right - rv);   // exact reference tie rule
        sy[j] = (float)(take_left ? (pos - 1) : pos);
        yy[j] = (take_left ? left : right) + mn[j];
    }
    so = make_float4(sy[0], sy[1], sy[2], sy[3]);
    yo = make_float4(yy[0], yy[1], yy[2], yy[3]);
}

__global__ void __launch_bounds__(NTHREADS, MINBLK)
quant_dequant_kernel(const float4* __restrict__ x4,
                     const float4* __restrict__ m4,
                     const float*  __restrict__ cb,
                     float* __restrict__ out_sym,
                     float* __restrict__ out_y,
                     int n4, int n)
{
    // Lane-private codebook replicas: entry i for lane l at s_cb[i*32 + l] ->
    // every data-dependent probe hits bank == lane (conflict-free).
    __shared__ float s_cb[LVL * 32];
    for (int i = threadIdx.x; i < LVL * 32; i += NTHREADS)
        s_cb[i] = cb[i >> 5];
    const float cb31 = __ldg(cb + 31);
    __syncthreads();

    const int    lane = threadIdx.x & 31;
    const float* mycb = s_cb + lane;           // mycb[idx*32] == cb[idx]

    const int stride = gridDim.x * NTHREADS;
    const int i0     = blockIdx.x * NTHREADS + threadIdx.x;

    int i = i0;
    // Main loop: both positions guaranteed valid -> 4 unconditional LDG.128.
    for (; i + stride < n4; i += 2 * stride) {
        const int i2 = i + stride;
        float4 xv1 = x4[i];
        float4 mv1 = m4[i];
        float4 xv2 = x4[i2];
        float4 mv2 = m4[i2];

        float4 so, yo;
        process4(xv1, mv1, mycb, cb31, so, yo);
        ((float4*)out_sym)[i] = so;
        ((float4*)out_y)[i]   = yo;

        process4(xv2, mv2, mycb, cb31, so, yo);
        ((float4*)out_sym)[i2] = so;
        ((float4*)out_y)[i2]   = yo;
    }
    // Epilogue: at most one remaining position.
    if (i < n4) {
        float4 xv = x4[i];
        float4 mv = m4[i];
        float4 so, yo;
        process4(xv, mv, mycb, cb31, so, yo);
        ((float4*)out_sym)[i] = so;
        ((float4*)out_y)[i]   = yo;
    }

    // Scalar tail (n not divisible by 4 — not expected here, but safe).
    int tail_start = n4 * 4;
    for (int t = tail_start + i0; t < n; t += stride) {
        const float* xs = (const float*)x4;
        const float* ms = (const float*)m4;
        float mvs = ms[t];
        float rv  = xs[t] - mvs;
        int pos = (cb31 < rv) ? 32 : 0;
        #pragma unroll
        for (int step = 16; step > 0; step >>= 1) {
            if (mycb[(pos + step - 1) << 5] < rv) pos += step;
        }
        pos = min(max(pos, 1), LVL - 1);
        float left  = mycb[(pos - 1) << 5];
        float right = mycb[pos << 5];
        bool take_left = (rv - left) <= (right - rv);
        out_sym[t] = (float)(take_left ? (pos - 1) : pos);
        out_y[t]   = (take_left ? left : right) + mvs;
    }
}

extern "C" void kernel_launch(void* const* d_in, const int* in_sizes, int n_in,
                              void* d_out, int out_size)
{
    const float* x     = (const float*)d_in[0];   // [B,C,H,W] f32
    const float* means = (const float*)d_in[1];   // [B,C,H,W] f32
    const float* cb    = (const float*)d_in[2];   // [64] f32 sorted

    int n  = in_sizes[0];
    int n4 = n >> 2;

    float* out_sym = (float*)d_out;       // first N floats: symbols (exact in f32)
    float* out_y   = out_sym + n;         // next  N floats: y_hat

    quant_dequant_kernel<<<NBLOCKS, NTHREADS>>>(
        (const float4*)x, (const float4*)means, cb, out_sym, out_y, n4, n);
}

// round 12
// speedup vs baseline: 1.1131x; 1.0164x over previous
#include <cuda_runtime.h>
#include <cuda_bf16.h>
#include <cstdint>

#define NTHREADS 256
#define MINBLK   6
#define NBLOCKS  (148 * MINBLK)
#define LVL      64

// Quantize/dequantize (AdaptedEntropyModel):
//   r = x - means
//   pos = clip(searchsorted(cb, r, side='left'), 1, 63)
//   sym = (r - cb[pos-1] <= cb[pos] - r) ? pos-1 : pos
//   y_hat = cb[sym] + means
// Output (out_size == 2N floats): [0..N) = float(sym), [N..2N) = y_hat.
//
// R11 = R10 skeleton (branch-free unroll-2, MLP_p1=4, plain STG,
// __launch_bounds__(256,6), grid 888) with a shorter per-element LDS chain:
//   - levels 32 and 16 probe registers (cb31; cb15/cb47 select)
//   - levels 8/4/2/1 probe the lane-replicated scalar codebook (4 LDS.32)
//   - final (left,right) neighbors come from ONE LDS.64 out of a
//     lane-replicated pair table pairs[i] = (cb[i-1], cb[i])
// Dependent chain per element: 7 LDS -> 5 (4x32b + 1x64b).

__device__ __forceinline__ void process4(float4 xv, float4 mv,
                                         const float*  __restrict__ mycb,
                                         const float2* __restrict__ mypr,
                                         float cb31, float cb15, float cb47,
                                         float4& so, float4& yo)
{
    float r[4]  = { xv.x - mv.x, xv.y - mv.y, xv.z - mv.z, xv.w - mv.w };
    float mn[4] = { mv.x, mv.y, mv.z, mv.w };
    float sy[4], yy[4];

    #pragma unroll
    for (int j = 0; j < 4; ++j) {
        const float rv = r[j];
        // levels 32, 16 from registers
        bool  t1  = (cb31 < rv);
        int   pos = t1 ? 32 : 0;
        float p16 = t1 ? cb47 : cb15;
        if (p16 < rv) pos += 16;
        // levels 8..1 from shared (conflict-free lane-replicated)
        #pragma unroll
        for (int step = 8; step > 0; step >>= 1) {
            if (mycb[(pos + step - 1) << 5] < rv) pos += step;
        }
        pos = max(pos, 1);                     // clip (max pos is 63 structurally)
        // fused neighbors: pairs[pos] = (cb[pos-1], cb[pos]), one LDS.64
        float2 pr = mypr[pos << 5];
        // Exact tie rule from the reference, same fp32 ops.
        bool take_left = (rv - pr.x) <= (pr.y - rv);
        sy[j] = (float)(take_left ? (pos - 1) : pos);
        yy[j] = (take_left ? pr.x : pr.y) + mn[j];
    }
    so = make_float4(sy[0], sy[1], sy[2], sy[3]);
    yo = make_float4(yy[0], yy[1], yy[2], yy[3]);
}

__global__ void __launch_bounds__(NTHREADS, MINBLK)
quant_dequant_kernel(const float4* __restrict__ x4,
                     const float4* __restrict__ m4,
                     const float*  __restrict__ cb,
                     float* __restrict__ out_sym,
                     float* __restrict__ out_y,
                     int n4, int n)
{
    // Lane-replicated tables: entry i for lane l at [i*32 + l].
    __shared__ float  s_cb[LVL * 32];          // 8 KB  (scalar probes)
    __shared__ float2 s_pr[LVL * 32];          // 16 KB (neighbor pairs)

    for (int i = threadIdx.x; i < LVL * 32; i += NTHREADS) {
        int e = i >> 5;
        s_cb[i] = cb[e];
        s_pr[i] = make_float2(cb[e > 0 ? e - 1 : 0], cb[e]);
    }
    const float cb15 = __ldg(cb + 15);
    const float cb31 = __ldg(cb + 31);
    const float cb47 = __ldg(cb + 47);
    __syncthreads();

    const int     lane = threadIdx.x & 31;
    const float*  mycb = s_cb + lane;          // mycb[e*32] == cb[e]
    const float2* mypr = s_pr + lane;          // mypr[e*32] == (cb[e-1], cb[e])

    const int stride = gridDim.x * NTHREADS;
    const int i0     = blockIdx.x * NTHREADS + threadIdx.x;

    int i = i0;
    // Main loop: both positions guaranteed valid -> 4 unconditional LDG.128.
    for (; i + stride < n4; i += 2 * stride) {
        const int i2 = i + stride;
        float4 xv1 = x4[i];
        float4 mv1 = m4[i];
        float4 xv2 = x4[i2];
        float4 mv2 = m4[i2];

        float4 so, yo;
        process4(xv1, mv1, mycb, mypr, cb31, cb15, cb47, so, yo);
        ((float4*)out_sym)[i] = so;
        ((float4*)out_y)[i]   = yo;

        process4(xv2, mv2, mycb, mypr, cb31, cb15, cb47, so, yo);
        ((float4*)out_sym)[i2] = so;
        ((float4*)out_y)[i2]   = yo;
    }
    // Epilogue: at most one remaining position.
    if (i < n4) {
        float4 xv = x4[i];
        float4 mv = m4[i];
        float4 so, yo;
        process4(xv, mv, mycb, mypr, cb31, cb15, cb47, so, yo);
        ((float4*)out_sym)[i] = so;
        ((float4*)out_y)[i]   = yo;
    }

    // Scalar tail (n not divisible by 4 — not expected here, but safe).
    int tail_start = n4 * 4;
    for (int t = tail_start + i0; t < n; t += stride) {
        const float* xs = (const float*)x4;
        const float* ms = (const float*)m4;
        float mvs = ms[t];
        float rv  = xs[t] - mvs;
        bool  t1  = (cb31 < rv);
        int   pos = t1 ? 32 : 0;
        float p16 = t1 ? cb47 : cb15;
        if (p16 < rv) pos += 16;
        #pragma unroll
        for (int step = 8; step > 0; step >>= 1) {
            if (mycb[(pos + step - 1) << 5] < rv) pos += step;
        }
        pos = max(pos, 1);
        float2 pr = mypr[pos << 5];
        bool take_left = (rv - pr.x) <= (pr.y - rv);
        out_sym[t] = (float)(take_left ? (pos - 1) : pos);
        out_y[t]   = (take_left ? pr.x : pr.y) + mvs;
    }
}

extern "C" void kernel_launch(void* const* d_in, const int* in_sizes, int n_in,
                              void* d_out, int out_size)
{
    const float* x     = (const float*)d_in[0];   // [B,C,H,W] f32
    const float* means = (const float*)d_in[1];   // [B,C,H,W] f32
    const float* cb    = (const float*)d_in[2];   // [64] f32 sorted

    int n  = in_sizes[0];
    int n4 = n >> 2;

    float* out_sym = (float*)d_out;       // first N floats: symbols (exact in f32)
    float* out_y   = out_sym + n;         // next  N floats: y_hat

    quant_dequant_kernel<<<NBLOCKS, NTHREADS>>>(
        (const float4*)x, (const float4*)means, cb, out_sym, out_y, n4, n);
}